// round 1
// baseline (speedup 1.0000x reference)
#include <cuda_runtime.h>
#include <cuda_bf16.h>
#include <math.h>

// ---------------- problem constants ----------------
#define BATCH 64
#define HH 56
#define WW_ 56
#define CDIM 128
#define L_TOK (HH * WW_)          // 3136
#define M_TOK (BATCH * L_TOK)     // 200704
#define NHEAD 4
#define HDIM 32
#define WS 7
#define NWIN_SIDE 8               // 56/7
#define NWIN (NWIN_SIDE * NWIN_SIDE) // 64 windows per image
#define NTOK 49                   // tokens per window
#define SHIFT 3
#define HIDDEN 512

// ---------------- scratch (static device globals; no runtime alloc) -------
__device__ float g_xw[(size_t)M_TOK * CDIM];      // LN1 output in window layout; reused as xn2
__device__ float g_qkv[(size_t)M_TOK * 3 * CDIM]; // qkv in window layout
__device__ float g_attn[(size_t)M_TOK * CDIM];    // attention output (window layout)
__device__ float g_x1[(size_t)M_TOK * CDIM];      // x after first residual (original layout)
__device__ float g_h[(size_t)M_TOK * HIDDEN];     // MLP hidden

__device__ __forceinline__ float warp_sum(float v) {
    #pragma unroll
    for (int o = 16; o > 0; o >>= 1) v += __shfl_xor_sync(0xffffffffu, v, o);
    return v;
}

// ---------------- LayerNorm (one warp per token) ----------------
// permute==1: write to shifted-window layout (LN1). permute==0: same row (LN2).
__global__ void __launch_bounds__(256) ln_kernel(
    const float* __restrict__ x, const float* __restrict__ g,
    const float* __restrict__ b, float* __restrict__ out, int permute)
{
    int warp = threadIdx.x >> 5, lane = threadIdx.x & 31;
    int t = blockIdx.x * 8 + warp;            // token row, < M_TOK (grid sized exactly)
    const float4 v = *(const float4*)(x + (size_t)t * CDIM + lane * 4);
    float mean = warp_sum(v.x + v.y + v.z + v.w) * (1.0f / 128.0f);
    float dx = v.x - mean, dy = v.y - mean, dz = v.z - mean, dw = v.w - mean;
    float var = warp_sum(dx*dx + dy*dy + dz*dz + dw*dw) * (1.0f / 128.0f);
    float inv = rsqrtf(var + 1e-5f);
    const float4 gv = *(const float4*)(g + lane * 4);
    const float4 bv = *(const float4*)(b + lane * 4);
    float4 o;
    o.x = dx * inv * gv.x + bv.x;
    o.y = dy * inv * gv.y + bv.y;
    o.z = dz * inv * gv.z + bv.z;
    o.w = dw * inv * gv.w + bv.w;

    int drow = t;
    if (permute) {
        int bimg = t / L_TOK;
        int l = t - bimg * L_TOK;
        int h = l / WW_, w = l - h * WW_;
        int hs = h - SHIFT; if (hs < 0) hs += HH;
        int ws = w - SHIFT; if (ws < 0) ws += WW_;
        int wh = hs / WS, ih = hs - wh * WS;
        int wwi = ws / WS, iw = ws - wwi * WS;
        drow = ((bimg * NWIN + wh * NWIN_SIDE + wwi) * NTOK) + ih * WS + iw;
    }
    *(float4*)(out + (size_t)drow * CDIM + lane * 4) = o;
}

// ---------------- tiled SGEMM, 64x64 tile, 256 threads, 4x4 per thread ----
// EPI: 0 = +bias            -> C[row*N+col]
//      1 = +bias +res(perm) -> C[prow*128+col]   (proj: window-reverse + unshift + residual)
//      2 = +bias, GELU      -> C[row*N+col]
//      3 = +bias +res[row]  -> C[row*N+col]      (fc2 + residual)
template<int EPI>
__global__ void __launch_bounds__(256) sgemm_kernel(
    const float* __restrict__ A, const float* __restrict__ B,
    const float* __restrict__ bias, const float* __restrict__ res,
    float* __restrict__ C, int M, int N, int K)
{
    __shared__ float As[32][64];   // [k][row]
    __shared__ float Bs[32][64];   // [k][col]

    int tid = threadIdx.x;
    int tx = tid & 15, ty = tid >> 4;
    int rowBase = blockIdx.y << 6;
    int colBase = blockIdx.x << 6;

    float acc[4][4];
    #pragma unroll
    for (int i = 0; i < 4; ++i)
        #pragma unroll
        for (int j = 0; j < 4; ++j) acc[i][j] = 0.0f;

    int ar = tid >> 3;              // 0..31
    int ac = (tid & 7) << 2;        // 0,4,...,28
    int br = tid >> 4;              // 0..15
    int bc = (tid & 15) << 2;       // 0..60

    for (int k0 = 0; k0 < K; k0 += 32) {
        float4 a0 = *(const float4*)(A + (size_t)(rowBase + ar) * K + k0 + ac);
        float4 a1 = *(const float4*)(A + (size_t)(rowBase + ar + 32) * K + k0 + ac);
        As[ac + 0][ar] = a0.x; As[ac + 1][ar] = a0.y;
        As[ac + 2][ar] = a0.z; As[ac + 3][ar] = a0.w;
        As[ac + 0][ar + 32] = a1.x; As[ac + 1][ar + 32] = a1.y;
        As[ac + 2][ar + 32] = a1.z; As[ac + 3][ar + 32] = a1.w;
        float4 b0 = *(const float4*)(B + (size_t)(k0 + br) * N + colBase + bc);
        float4 b1 = *(const float4*)(B + (size_t)(k0 + br + 16) * N + colBase + bc);
        *(float4*)&Bs[br][bc] = b0;
        *(float4*)&Bs[br + 16][bc] = b1;
        __syncthreads();

        #pragma unroll
        for (int kk = 0; kk < 32; ++kk) {
            float4 av = *(const float4*)&As[kk][ty << 2];
            float4 bv = *(const float4*)&Bs[kk][tx << 2];
            float a[4] = {av.x, av.y, av.z, av.w};
            float bb[4] = {bv.x, bv.y, bv.z, bv.w};
            #pragma unroll
            for (int i = 0; i < 4; ++i)
                #pragma unroll
                for (int j = 0; j < 4; ++j)
                    acc[i][j] += a[i] * bb[j];
        }
        __syncthreads();
    }

    float bvals[4];
    #pragma unroll
    for (int j = 0; j < 4; ++j) bvals[j] = bias[colBase + (tx << 2) + j];

    #pragma unroll
    for (int i = 0; i < 4; ++i) {
        int row = rowBase + (ty << 2) + i;
        int prow = row;
        if (EPI == 1) {
            int win = row / NTOK, tt = row - win * NTOK;
            int bimg = win >> 6, wloc = win & 63;
            int wh = wloc >> 3, wwi = wloc & 7;
            int ih = tt / WS, iw = tt - ih * WS;
            int hs = wh * WS + ih, ws = wwi * WS + iw;
            int h = hs + SHIFT; if (h >= HH) h -= HH;
            int w = ws + SHIFT; if (w >= WW_) w -= WW_;
            prow = bimg * L_TOK + h * WW_ + w;
        }
        #pragma unroll
        for (int j = 0; j < 4; ++j) {
            int col = colBase + (tx << 2) + j;
            float v = acc[i][j] + bvals[j];
            if (EPI == 0) {
                C[(size_t)row * N + col] = v;
            } else if (EPI == 1) {
                C[(size_t)prow * CDIM + col] = v + res[(size_t)prow * CDIM + col];
            } else if (EPI == 2) {
                C[(size_t)row * N + col] = 0.5f * v * (1.0f + erff(v * 0.70710678118654752f));
            } else { // 3
                C[(size_t)row * N + col] = v + res[(size_t)row * N + col];
            }
        }
    }
}

// ---------------- windowed attention: one block per (window, head) --------
__global__ void __launch_bounds__(256) attn_kernel(
    const float* __restrict__ qkv, const float* __restrict__ bias_table,
    float* __restrict__ out)
{
    __shared__ float Qs[NTOK * 33];
    __shared__ float Ks[NTOK * 33];
    __shared__ float Vs[NTOK * 33];
    __shared__ float S[NTOK * NTOK];
    __shared__ unsigned char grp[NTOK];

    int win = blockIdx.x;
    int head = blockIdx.y;
    int tid = threadIdx.x;
    int wloc = win & 63;
    int wh = wloc >> 3, wwi = wloc & 7;

    size_t base = (size_t)win * NTOK * (3 * CDIM) + head * HDIM;
    for (int idx = tid; idx < NTOK * HDIM; idx += 256) {
        int n = idx >> 5, d = idx & 31;
        size_t r = base + (size_t)n * (3 * CDIM) + d;
        Qs[n * 33 + d] = qkv[r];
        Ks[n * 33 + d] = qkv[r + CDIM];
        Vs[n * 33 + d] = qkv[r + 2 * CDIM];
    }
    if (tid < NTOK) {
        int ih = tid / WS, iw = tid - ih * WS;
        int hs = wh * WS + ih, ws = wwi * WS + iw;
        int gh = hs < (HH - WS) ? 0 : (hs < (HH - SHIFT) ? 1 : 2);
        int gw = ws < (WW_ - WS) ? 0 : (ws < (WW_ - SHIFT) ? 1 : 2);
        grp[tid] = (unsigned char)(gh * 3 + gw);
    }
    __syncthreads();

    const float scale = 0.17677669529663689f;  // 1/sqrt(32)
    for (int idx = tid; idx < NTOK * NTOK; idx += 256) {
        int i = idx / NTOK, j = idx - i * NTOK;
        const float* qi = Qs + i * 33;
        const float* kj = Ks + j * 33;
        float s = 0.0f;
        #pragma unroll
        for (int d = 0; d < HDIM; ++d) s += qi[d] * kj[d];
        int dh = i / WS - j / WS + (WS - 1);
        int dw = i % WS - j % WS + (WS - 1);
        float bv = bias_table[(dh * (2 * WS - 1) + dw) * NHEAD + head];
        float m = (grp[i] != grp[j]) ? -100.0f : 0.0f;
        S[idx] = s * scale + bv + m;
    }
    __syncthreads();

    int warp = tid >> 5, lane = tid & 31;
    for (int i = warp; i < NTOK; i += 8) {
        float* row = S + i * NTOK;
        float v0 = row[lane];
        float v1 = (lane < NTOK - 32) ? row[lane + 32] : -1e30f;
        float m = fmaxf(v0, v1);
        #pragma unroll
        for (int o = 16; o > 0; o >>= 1) m = fmaxf(m, __shfl_xor_sync(0xffffffffu, m, o));
        float e0 = expf(v0 - m);
        float e1 = (lane < NTOK - 32) ? expf(v1 - m) : 0.0f;
        float sum = warp_sum(e0 + e1);
        float inv = 1.0f / sum;
        row[lane] = e0 * inv;
        if (lane < NTOK - 32) row[lane + 32] = e1 * inv;
    }
    __syncthreads();

    size_t obase = (size_t)win * NTOK * CDIM + head * HDIM;
    for (int idx = tid; idx < NTOK * HDIM; idx += 256) {
        int i = idx >> 5, c = idx & 31;
        const float* srow = S + i * NTOK;
        float acc = 0.0f;
        #pragma unroll
        for (int j = 0; j < NTOK; ++j) acc += srow[j] * Vs[j * 33 + c];
        out[obase + (size_t)i * CDIM + c] = acc;
    }
}

// ---------------- host launcher ----------------
extern "C" void kernel_launch(void* const* d_in, const int* in_sizes, int n_in,
                              void* d_out, int out_size)
{
    const float* x        = (const float*)d_in[0];
    const float* norm1_g  = (const float*)d_in[1];
    const float* norm1_b  = (const float*)d_in[2];
    const float* qkv_w    = (const float*)d_in[3];
    const float* qkv_b    = (const float*)d_in[4];
    const float* rel_tab  = (const float*)d_in[5];
    const float* proj_w   = (const float*)d_in[6];
    const float* proj_b   = (const float*)d_in[7];
    const float* norm2_g  = (const float*)d_in[8];
    const float* norm2_b  = (const float*)d_in[9];
    const float* fc1_w    = (const float*)d_in[10];
    const float* fc1_b    = (const float*)d_in[11];
    const float* fc2_w    = (const float*)d_in[12];
    const float* fc2_b    = (const float*)d_in[13];
    float* out = (float*)d_out;

    float *xw, *qkv, *attn, *x1, *h;
    cudaGetSymbolAddress((void**)&xw,   g_xw);
    cudaGetSymbolAddress((void**)&qkv,  g_qkv);
    cudaGetSymbolAddress((void**)&attn, g_attn);
    cudaGetSymbolAddress((void**)&x1,   g_x1);
    cudaGetSymbolAddress((void**)&h,    g_h);

    const int M = M_TOK;

    // 1) LN1 + shift + window partition
    ln_kernel<<<M / 8, 256>>>(x, norm1_g, norm1_b, xw, 1);

    // 2) QKV GEMM  [M,128] x [128,384]
    sgemm_kernel<0><<<dim3(384 / 64, M / 64), 256>>>(xw, qkv_w, qkv_b, nullptr, qkv, M, 384, 128);

    // 3) windowed attention (per window, per head)
    attn_kernel<<<dim3(M / NTOK, NHEAD), 256>>>(qkv, rel_tab, attn);

    // 4) proj GEMM + window reverse + unshift + residual
    sgemm_kernel<1><<<dim3(128 / 64, M / 64), 256>>>(attn, proj_w, proj_b, x, x1, M, 128, 128);

    // 5) LN2 (reuse xw as xn2 buffer)
    ln_kernel<<<M / 8, 256>>>(x1, norm2_g, norm2_b, xw, 0);

    // 6) FC1 GEMM + GELU
    sgemm_kernel<2><<<dim3(HIDDEN / 64, M / 64), 256>>>(xw, fc1_w, fc1_b, nullptr, h, M, HIDDEN, 128);

    // 7) FC2 GEMM + residual -> d_out
    sgemm_kernel<3><<<dim3(128 / 64, M / 64), 256>>>(h, fc2_w, fc2_b, x1, out, M, 128, HIDDEN);
}

// round 3
// speedup vs baseline: 2.8422x; 2.8422x over previous
#include <cuda_runtime.h>
#include <cuda_bf16.h>
#include <math.h>
#include <stdint.h>

// ---------------- problem constants ----------------
#define BATCH 64
#define HH 56
#define WW_ 56
#define CDIM 128
#define L_TOK (HH * WW_)            // 3136
#define M_TOK (BATCH * L_TOK)       // 200704
#define NHEAD 4
#define HDIM 32
#define WS 7
#define NWIN_SIDE 8
#define NTOK 49
#define SHIFT 3
#define HIDDEN 512

// weight-transpose buffer offsets (bf16 [N,K] layouts)
#define WQ_OFF 0            // 384*128
#define WP_OFF 49152        // 128*128
#define W1_OFF 65536        // 512*128
#define W2_OFF 131072       // 128*512
#define WT_TOTAL 196608

// ---------------- scratch ----------------
__device__ __nv_bfloat16 g_xwb[(size_t)M_TOK * CDIM];
__device__ __nv_bfloat16 g_qkvb[(size_t)M_TOK * 3 * CDIM];
__device__ __nv_bfloat16 g_attnb[(size_t)M_TOK * CDIM];
__device__ __nv_bfloat16 g_hb[(size_t)M_TOK * HIDDEN];
__device__ float g_x1[(size_t)M_TOK * CDIM];
__device__ __nv_bfloat16 g_wT[WT_TOTAL];

__device__ __forceinline__ uint32_t smem_u32(const void* p) {
    uint32_t a;
    asm("{ .reg .u64 t; cvta.to.shared.u64 t, %1; cvt.u32.u64 %0, t; }" : "=r"(a) : "l"(p));
    return a;
}
__device__ __forceinline__ float warp_sum(float v) {
    #pragma unroll
    for (int o = 16; o > 0; o >>= 1) v += __shfl_xor_sync(0xffffffffu, v, o);
    return v;
}
__device__ __forceinline__ uint32_t pack_bf2(float a, float b) {
    __nv_bfloat162 t = __floats2bfloat162_rn(a, b);
    return *reinterpret_cast<uint32_t*>(&t);
}

#define LDSM_X4(r0, r1, r2, r3, addr) \
    asm volatile("ldmatrix.sync.aligned.m8n8.x4.shared.b16 {%0,%1,%2,%3}, [%4];" \
        : "=r"(r0), "=r"(r1), "=r"(r2), "=r"(r3) : "r"(addr))

#define MMA_BF16(c, a, b0, b1) \
    asm volatile("mma.sync.aligned.m16n8k16.row.col.f32.bf16.bf16.f32 " \
        "{%0,%1,%2,%3}, {%4,%5,%6,%7}, {%8,%9}, {%0,%1,%2,%3};" \
        : "+f"((c)[0]), "+f"((c)[1]), "+f"((c)[2]), "+f"((c)[3]) \
        : "r"((a)[0]), "r"((a)[1]), "r"((a)[2]), "r"((a)[3]), "r"(b0), "r"(b1))

// ---------------- weight transpose + bf16 convert ----------------
__global__ void __launch_bounds__(256) convert_w_kernel(
    const float* __restrict__ qkv_w, const float* __restrict__ proj_w,
    const float* __restrict__ fc1_w, const float* __restrict__ fc2_w,
    __nv_bfloat16* __restrict__ wT)
{
    int i = blockIdx.x * 256 + threadIdx.x;
    if (i < WQ_OFF + 49152) {
        int j = i - WQ_OFF; int n = j / 128, k = j % 128;
        wT[i] = __float2bfloat16(qkv_w[k * 384 + n]);
    } else if (i < WP_OFF + 16384) {
        int j = i - WP_OFF; int n = j / 128, k = j % 128;
        wT[i] = __float2bfloat16(proj_w[k * 128 + n]);
    } else if (i < W1_OFF + 65536) {
        int j = i - W1_OFF; int n = j / 128, k = j % 128;
        wT[i] = __float2bfloat16(fc1_w[k * 512 + n]);
    } else if (i < W2_OFF + 65536) {
        int j = i - W2_OFF; int n = j / 512, k = j % 512;
        wT[i] = __float2bfloat16(fc2_w[k * 128 + n]);
    }
}

// ---------------- LayerNorm -> bf16 (optional shifted-window permute) ----
__global__ void __launch_bounds__(256) ln_kernel(
    const float* __restrict__ x, const float* __restrict__ g,
    const float* __restrict__ b, __nv_bfloat16* __restrict__ out, int permute)
{
    int warp = threadIdx.x >> 5, lane = threadIdx.x & 31;
    int t = blockIdx.x * 8 + warp;
    const float4 v = *(const float4*)(x + (size_t)t * CDIM + lane * 4);
    float mean = warp_sum(v.x + v.y + v.z + v.w) * (1.0f / 128.0f);
    float dx = v.x - mean, dy = v.y - mean, dz = v.z - mean, dw = v.w - mean;
    float var = warp_sum(dx*dx + dy*dy + dz*dz + dw*dw) * (1.0f / 128.0f);
    float inv = rsqrtf(var + 1e-5f);
    const float4 gv = *(const float4*)(g + lane * 4);
    const float4 bv = *(const float4*)(b + lane * 4);
    float o0 = dx * inv * gv.x + bv.x;
    float o1 = dy * inv * gv.y + bv.y;
    float o2 = dz * inv * gv.z + bv.z;
    float o3 = dw * inv * gv.w + bv.w;

    int drow = t;
    if (permute) {
        int bimg = t / L_TOK;
        int l = t - bimg * L_TOK;
        int h = l / WW_, w = l - h * WW_;
        int hs = h - SHIFT; if (hs < 0) hs += HH;
        int ws = w - SHIFT; if (ws < 0) ws += WW_;
        int wh = hs / WS, ih = hs - wh * WS;
        int wwi = ws / WS, iw = ws - wwi * WS;
        drow = ((bimg * 64 + wh * NWIN_SIDE + wwi) * NTOK) + ih * WS + iw;
    }
    uint2 u;
    u.x = pack_bf2(o0, o1);
    u.y = pack_bf2(o2, o3);
    *(uint2*)(out + (size_t)drow * CDIM + lane * 4) = u;
}

// ---------------- HMMA bf16 GEMM: 128x128 tile, BK=64, 8 warps ----------
// A: [M,K] bf16 row-major.  Bt: [N,K] bf16 row-major (i.e. B^T).
// EPI 0: +bias -> bf16 C[row*N+col]                 (qkv)
// EPI 1: +bias +res, permuted row -> f32 [prow*128]  (proj: reverse+unshift+residual)
// EPI 2: +bias, GELU -> bf16                         (fc1)
// EPI 3: +bias +res[row*N] -> f32                    (fc2 + residual)
#define SAS 72   // smem row stride in bf16 (64 data + 8 pad)
template<int EPI>
__global__ void __launch_bounds__(256) gemm_mma(
    const __nv_bfloat16* __restrict__ A, const __nv_bfloat16* __restrict__ Bt,
    const float* __restrict__ bias, const float* __restrict__ res,
    void* __restrict__ Cout, int M, int N, int K)
{
    __shared__ __align__(16) __nv_bfloat16 sA[128 * SAS];
    __shared__ __align__(16) __nv_bfloat16 sB[128 * SAS];

    const int tid = threadIdx.x;
    const int wid = tid >> 5, lane = tid & 31;
    const int rowBase = blockIdx.y << 7;
    const int colBase = blockIdx.x << 7;

    const int wm = wid & 3;          // warp row group: 32 rows
    const int wn = wid >> 2;         // warp col group: 64 cols
    const int mBase = wm * 32;
    const int nBase = wn * 64;

    const uint32_t uA = smem_u32(sA), uB = smem_u32(sB);

    // ldmatrix per-lane addressing components
    const int mat = lane >> 3;                        // 0..3
    const int aRowOff = (lane & 7) + (mat & 1) * 8;   // A: matrix bit0 -> +8 rows
    const int aKOff = (mat >> 1) * 8;                 //    matrix bit1 -> +8 k
    const int bRowOff = (lane & 7) + ((mat >> 1) & 1) * 8;  // B: bit1 -> +8 n-rows
    const int bKOff = (mat & 1) * 8;                        //    bit0 -> +8 k

    float acc[2][8][4];
    #pragma unroll
    for (int i = 0; i < 2; ++i)
        #pragma unroll
        for (int j = 0; j < 8; ++j)
            #pragma unroll
            for (int t = 0; t < 4; ++t) acc[i][j][t] = 0.0f;

    const int nc = K >> 6;
    const int kq = K >> 3;   // global row stride in uint4

    for (int c = 0; c < nc; ++c) {
        const uint4* Ag = (const uint4*)(A + (size_t)rowBase * K + (size_t)c * 64);
        const uint4* Bg = (const uint4*)(Bt + (size_t)colBase * K + (size_t)c * 64);
        #pragma unroll
        for (int it = 0; it < 4; ++it) {
            int i = tid + it * 256;
            int row = i >> 3, q = i & 7;
            *(uint4*)&sA[row * SAS + q * 8] = Ag[(size_t)row * kq + q];
            *(uint4*)&sB[row * SAS + q * 8] = Bg[(size_t)row * kq + q];
        }
        __syncthreads();

        #pragma unroll
        for (int kk = 0; kk < 4; ++kk) {
            const int k0 = kk * 16;
            uint32_t a[2][4];
            #pragma unroll
            for (int mf = 0; mf < 2; ++mf) {
                uint32_t addr = uA + ((mBase + mf * 16 + aRowOff) * SAS + k0 + aKOff) * 2;
                LDSM_X4(a[mf][0], a[mf][1], a[mf][2], a[mf][3], addr);
            }
            #pragma unroll
            for (int nn = 0; nn < 4; ++nn) {
                uint32_t b0, b1, b2, b3;
                uint32_t addr = uB + ((nBase + nn * 16 + bRowOff) * SAS + k0 + bKOff) * 2;
                LDSM_X4(b0, b1, b2, b3, addr);
                #pragma unroll
                for (int mf = 0; mf < 2; ++mf) {
                    MMA_BF16(acc[mf][nn * 2 + 0], a[mf], b0, b1);
                    MMA_BF16(acc[mf][nn * 2 + 1], a[mf], b2, b3);
                }
            }
        }
        __syncthreads();
    }

    // ---------------- epilogue ----------------
    const int g4 = lane >> 2, t4 = lane & 3;
    float2 bias2[8];
    #pragma unroll
    for (int nf = 0; nf < 8; ++nf) {
        int col = colBase + nBase + nf * 8 + 2 * t4;
        bias2[nf] = *(const float2*)&bias[col];
    }

    #pragma unroll
    for (int mf = 0; mf < 2; ++mf) {
        #pragma unroll
        for (int rr = 0; rr < 2; ++rr) {
            const int m = rowBase + mBase + mf * 16 + g4 + rr * 8;
            int prow = m;
            if (EPI == 1) {
                int win = m / NTOK, tt = m - win * NTOK;
                int bimg = win >> 6, wloc = win & 63;
                int wh = wloc >> 3, wwi = wloc & 7;
                int ih = tt / WS, iw = tt - ih * WS;
                int h = wh * WS + ih + SHIFT; if (h >= HH) h -= HH;
                int w = wwi * WS + iw + SHIFT; if (w >= WW_) w -= WW_;
                prow = bimg * L_TOK + h * WW_ + w;
            }
            #pragma unroll
            for (int nf = 0; nf < 8; ++nf) {
                const int col = colBase + nBase + nf * 8 + 2 * t4;
                float v0 = acc[mf][nf][rr * 2 + 0] + bias2[nf].x;
                float v1 = acc[mf][nf][rr * 2 + 1] + bias2[nf].y;
                if (EPI == 2) {
                    v0 = 0.5f * v0 * (1.0f + erff(v0 * 0.70710678118654752f));
                    v1 = 0.5f * v1 * (1.0f + erff(v1 * 0.70710678118654752f));
                }
                if (EPI == 0 || EPI == 2) {
                    __nv_bfloat16* C = (__nv_bfloat16*)Cout;
                    uint32_t u = pack_bf2(v0, v1);
                    *(uint32_t*)&C[(size_t)m * N + col] = u;
                } else {
                    float* C = (float*)Cout;
                    const size_t o = (EPI == 1) ? ((size_t)prow * CDIM + col)
                                                : ((size_t)m * N + col);
                    float2 rv = *(const float2*)&res[o];
                    float2 ov; ov.x = v0 + rv.x; ov.y = v1 + rv.y;
                    *(float2*)&C[o] = ov;
                }
            }
        }
    }
}

// ---------------- windowed attention (bf16 in/out) ----------------
__global__ void __launch_bounds__(256) attn_kernel(
    const __nv_bfloat16* __restrict__ qkv, const float* __restrict__ bias_table,
    __nv_bfloat16* __restrict__ out)
{
    __shared__ float Qs[NTOK * 33];
    __shared__ float Ks[NTOK * 33];
    __shared__ float Vs[NTOK * 33];
    __shared__ float S[NTOK * NTOK];
    __shared__ unsigned char grp[NTOK];

    int win = blockIdx.x;
    int head = blockIdx.y;
    int tid = threadIdx.x;
    int wloc = win & 63;
    int wh = wloc >> 3, wwi = wloc & 7;

    size_t base = (size_t)win * NTOK * (3 * CDIM) + head * HDIM;
    for (int idx = tid; idx < NTOK * HDIM; idx += 256) {
        int n = idx >> 5, d = idx & 31;
        size_t r = base + (size_t)n * (3 * CDIM) + d;
        Qs[n * 33 + d] = __bfloat162float(qkv[r]);
        Ks[n * 33 + d] = __bfloat162float(qkv[r + CDIM]);
        Vs[n * 33 + d] = __bfloat162float(qkv[r + 2 * CDIM]);
    }
    if (tid < NTOK) {
        int ih = tid / WS, iw = tid - ih * WS;
        int hs = wh * WS + ih, ws = wwi * WS + iw;
        int gh = hs < (HH - WS) ? 0 : (hs < (HH - SHIFT) ? 1 : 2);
        int gw = ws < (WW_ - WS) ? 0 : (ws < (WW_ - SHIFT) ? 1 : 2);
        grp[tid] = (unsigned char)(gh * 3 + gw);
    }
    __syncthreads();

    const float scale = 0.17677669529663689f;
    for (int idx = tid; idx < NTOK * NTOK; idx += 256) {
        int i = idx / NTOK, j = idx - i * NTOK;
        const float* qi = Qs + i * 33;
        const float* kj = Ks + j * 33;
        float s = 0.0f;
        #pragma unroll
        for (int d = 0; d < HDIM; ++d) s += qi[d] * kj[d];
        int dh = i / WS - j / WS + (WS - 1);
        int dw = i % WS - j % WS + (WS - 1);
        float bv = bias_table[(dh * (2 * WS - 1) + dw) * NHEAD + head];
        float mk = (grp[i] != grp[j]) ? -100.0f : 0.0f;
        S[idx] = s * scale + bv + mk;
    }
    __syncthreads();

    int warp = tid >> 5, lane = tid & 31;
    for (int i = warp; i < NTOK; i += 8) {
        float* row = S + i * NTOK;
        float v0 = row[lane];
        float v1 = (lane < NTOK - 32) ? row[lane + 32] : -1e30f;
        float mx = fmaxf(v0, v1);
        #pragma unroll
        for (int o = 16; o > 0; o >>= 1) mx = fmaxf(mx, __shfl_xor_sync(0xffffffffu, mx, o));
        float e0 = expf(v0 - mx);
        float e1 = (lane < NTOK - 32) ? expf(v1 - mx) : 0.0f;
        float sum = warp_sum(e0 + e1);
        float inv = 1.0f / sum;
        row[lane] = e0 * inv;
        if (lane < NTOK - 32) row[lane + 32] = e1 * inv;
    }
    __syncthreads();

    size_t obase = (size_t)win * NTOK * CDIM + head * HDIM;
    for (int idx = tid; idx < NTOK * HDIM; idx += 256) {
        int i = idx >> 5, c = idx & 31;
        const float* srow = S + i * NTOK;
        float acc = 0.0f;
        #pragma unroll
        for (int j = 0; j < NTOK; ++j) acc += srow[j] * Vs[j * 33 + c];
        out[obase + (size_t)i * CDIM + c] = __float2bfloat16(acc);
    }
}

// ---------------- host launcher ----------------
extern "C" void kernel_launch(void* const* d_in, const int* in_sizes, int n_in,
                              void* d_out, int out_size)
{
    const float* x        = (const float*)d_in[0];
    const float* norm1_g  = (const float*)d_in[1];
    const float* norm1_b  = (const float*)d_in[2];
    const float* qkv_w    = (const float*)d_in[3];
    const float* qkv_b    = (const float*)d_in[4];
    const float* rel_tab  = (const float*)d_in[5];
    const float* proj_w   = (const float*)d_in[6];
    const float* proj_b   = (const float*)d_in[7];
    const float* norm2_g  = (const float*)d_in[8];
    const float* norm2_b  = (const float*)d_in[9];
    const float* fc1_w    = (const float*)d_in[10];
    const float* fc1_b    = (const float*)d_in[11];
    const float* fc2_w    = (const float*)d_in[12];
    const float* fc2_b    = (const float*)d_in[13];
    float* out = (float*)d_out;

    __nv_bfloat16 *xwb, *qkvb, *attnb, *hb, *wT;
    float* x1;
    cudaGetSymbolAddress((void**)&xwb,   g_xwb);
    cudaGetSymbolAddress((void**)&qkvb,  g_qkvb);
    cudaGetSymbolAddress((void**)&attnb, g_attnb);
    cudaGetSymbolAddress((void**)&hb,    g_hb);
    cudaGetSymbolAddress((void**)&wT,    g_wT);
    cudaGetSymbolAddress((void**)&x1,    g_x1);

    const int M = M_TOK;

    // 0) weights -> bf16 [N,K]
    convert_w_kernel<<<WT_TOTAL / 256, 256>>>(qkv_w, proj_w, fc1_w, fc2_w, wT);

    // 1) LN1 + shift + window partition -> bf16
    ln_kernel<<<M / 8, 256>>>(x, norm1_g, norm1_b, xwb, 1);

    // 2) QKV GEMM (HMMA)
    gemm_mma<0><<<dim3(3, M / 128), 256>>>(xwb, wT + WQ_OFF, qkv_b, nullptr, qkvb, M, 384, 128);

    // 3) windowed attention
    attn_kernel<<<dim3(M / NTOK, NHEAD), 256>>>(qkvb, rel_tab, attnb);

    // 4) proj GEMM + reverse/unshift + residual -> fp32 x1
    gemm_mma<1><<<dim3(1, M / 128), 256>>>(attnb, wT + WP_OFF, proj_b, x, x1, M, 128, 128);

    // 5) LN2 -> bf16
    ln_kernel<<<M / 8, 256>>>(x1, norm2_g, norm2_b, xwb, 0);

    // 6) FC1 GEMM + GELU -> bf16 h
    gemm_mma<2><<<dim3(4, M / 128), 256>>>(xwb, wT + W1_OFF, fc1_b, nullptr, hb, M, 512, 128);

    // 7) FC2 GEMM + residual -> fp32 out
    gemm_mma<3><<<dim3(1, M / 128), 256>>>(hb, wT + W2_OFF, fc2_b, x1, out, M, 128, 512);
}

// round 4
// speedup vs baseline: 4.3550x; 1.5323x over previous
#include <cuda_runtime.h>
#include <cuda_bf16.h>
#include <math.h>
#include <stdint.h>

// ---------------- problem constants ----------------
#define BATCH 64
#define HH 56
#define WW_ 56
#define CDIM 128
#define L_TOK (HH * WW_)            // 3136
#define M_TOK (BATCH * L_TOK)       // 200704
#define NHEAD 4
#define HDIM 32
#define WS 7
#define NWIN_SIDE 8
#define NTOK 49
#define SHIFT 3
#define HIDDEN 512

// weight-transpose buffer offsets (bf16 [N,K] layouts)
#define WQ_OFF 0            // 384*128
#define WP_OFF 49152        // 128*128
#define W1_OFF 65536        // 512*128
#define W2_OFF 131072       // 128*512
#define WT_TOTAL 196608

// ---------------- scratch ----------------
__device__ __nv_bfloat16 g_xwb[(size_t)M_TOK * CDIM];
__device__ __nv_bfloat16 g_qkvb[(size_t)M_TOK * 3 * CDIM];
__device__ __nv_bfloat16 g_attnb[(size_t)M_TOK * CDIM];
__device__ __nv_bfloat16 g_hb[(size_t)M_TOK * HIDDEN];
__device__ float g_x1[(size_t)M_TOK * CDIM];
__device__ __nv_bfloat16 g_wT[WT_TOTAL];

__device__ __forceinline__ uint32_t smem_u32(const void* p) {
    uint32_t a;
    asm("{ .reg .u64 t; cvta.to.shared.u64 t, %1; cvt.u32.u64 %0, t; }" : "=r"(a) : "l"(p));
    return a;
}
__device__ __forceinline__ float warp_sum(float v) {
    #pragma unroll
    for (int o = 16; o > 0; o >>= 1) v += __shfl_xor_sync(0xffffffffu, v, o);
    return v;
}
__device__ __forceinline__ uint32_t pack_bf2(float a, float b) {
    __nv_bfloat162 t = __floats2bfloat162_rn(a, b);
    return *reinterpret_cast<uint32_t*>(&t);
}

#define LDSM_X4(r0, r1, r2, r3, addr) \
    asm volatile("ldmatrix.sync.aligned.m8n8.x4.shared.b16 {%0,%1,%2,%3}, [%4];" \
        : "=r"(r0), "=r"(r1), "=r"(r2), "=r"(r3) : "r"(addr))

#define MMA_BF16(c, a, b0, b1) \
    asm volatile("mma.sync.aligned.m16n8k16.row.col.f32.bf16.bf16.f32 " \
        "{%0,%1,%2,%3}, {%4,%5,%6,%7}, {%8,%9}, {%0,%1,%2,%3};" \
        : "+f"((c)[0]), "+f"((c)[1]), "+f"((c)[2]), "+f"((c)[3]) \
        : "r"((a)[0]), "r"((a)[1]), "r"((a)[2]), "r"((a)[3]), "r"(b0), "r"(b1))

// ---------------- weight transpose + bf16 convert ----------------
__global__ void __launch_bounds__(256) convert_w_kernel(
    const float* __restrict__ qkv_w, const float* __restrict__ proj_w,
    const float* __restrict__ fc1_w, const float* __restrict__ fc2_w,
    __nv_bfloat16* __restrict__ wT)
{
    int i = blockIdx.x * 256 + threadIdx.x;
    if (i < WQ_OFF + 49152) {
        int j = i - WQ_OFF; int n = j / 128, k = j % 128;
        wT[i] = __float2bfloat16(qkv_w[k * 384 + n]);
    } else if (i < WP_OFF + 16384) {
        int j = i - WP_OFF; int n = j / 128, k = j % 128;
        wT[i] = __float2bfloat16(proj_w[k * 128 + n]);
    } else if (i < W1_OFF + 65536) {
        int j = i - W1_OFF; int n = j / 128, k = j % 128;
        wT[i] = __float2bfloat16(fc1_w[k * 512 + n]);
    } else if (i < W2_OFF + 65536) {
        int j = i - W2_OFF; int n = j / 512, k = j % 512;
        wT[i] = __float2bfloat16(fc2_w[k * 128 + n]);
    }
}

// ---------------- LayerNorm -> bf16 (optional shifted-window permute) ----
__global__ void __launch_bounds__(256) ln_kernel(
    const float* __restrict__ x, const float* __restrict__ g,
    const float* __restrict__ b, __nv_bfloat16* __restrict__ out, int permute)
{
    int warp = threadIdx.x >> 5, lane = threadIdx.x & 31;
    int t = blockIdx.x * 8 + warp;
    const float4 v = *(const float4*)(x + (size_t)t * CDIM + lane * 4);
    float mean = warp_sum(v.x + v.y + v.z + v.w) * (1.0f / 128.0f);
    float dx = v.x - mean, dy = v.y - mean, dz = v.z - mean, dw = v.w - mean;
    float var = warp_sum(dx*dx + dy*dy + dz*dz + dw*dw) * (1.0f / 128.0f);
    float inv = rsqrtf(var + 1e-5f);
    const float4 gv = *(const float4*)(g + lane * 4);
    const float4 bv = *(const float4*)(b + lane * 4);
    float o0 = dx * inv * gv.x + bv.x;
    float o1 = dy * inv * gv.y + bv.y;
    float o2 = dz * inv * gv.z + bv.z;
    float o3 = dw * inv * gv.w + bv.w;

    int drow = t;
    if (permute) {
        int bimg = t / L_TOK;
        int l = t - bimg * L_TOK;
        int h = l / WW_, w = l - h * WW_;
        int hs = h - SHIFT; if (hs < 0) hs += HH;
        int ws = w - SHIFT; if (ws < 0) ws += WW_;
        int wh = hs / WS, ih = hs - wh * WS;
        int wwi = ws / WS, iw = ws - wwi * WS;
        drow = ((bimg * 64 + wh * NWIN_SIDE + wwi) * NTOK) + ih * WS + iw;
    }
    uint2 u;
    u.x = pack_bf2(o0, o1);
    u.y = pack_bf2(o2, o3);
    *(uint2*)(out + (size_t)drow * CDIM + lane * 4) = u;
}

// ---------------- HMMA bf16 GEMM: 128x128 tile, BK=64, 8 warps ----------
#define SAS 72
template<int EPI>
__global__ void __launch_bounds__(256) gemm_mma(
    const __nv_bfloat16* __restrict__ A, const __nv_bfloat16* __restrict__ Bt,
    const float* __restrict__ bias, const float* __restrict__ res,
    void* __restrict__ Cout, int M, int N, int K)
{
    __shared__ __align__(16) __nv_bfloat16 sA[128 * SAS];
    __shared__ __align__(16) __nv_bfloat16 sB[128 * SAS];

    const int tid = threadIdx.x;
    const int wid = tid >> 5, lane = tid & 31;
    const int rowBase = blockIdx.y << 7;
    const int colBase = blockIdx.x << 7;

    const int wm = wid & 3;
    const int wn = wid >> 2;
    const int mBase = wm * 32;
    const int nBase = wn * 64;

    const uint32_t uA = smem_u32(sA), uB = smem_u32(sB);

    const int mat = lane >> 3;
    const int aRowOff = (lane & 7) + (mat & 1) * 8;
    const int aKOff = (mat >> 1) * 8;
    const int bRowOff = (lane & 7) + ((mat >> 1) & 1) * 8;
    const int bKOff = (mat & 1) * 8;

    float acc[2][8][4];
    #pragma unroll
    for (int i = 0; i < 2; ++i)
        #pragma unroll
        for (int j = 0; j < 8; ++j)
            #pragma unroll
            for (int t = 0; t < 4; ++t) acc[i][j][t] = 0.0f;

    const int nc = K >> 6;
    const int kq = K >> 3;

    for (int c = 0; c < nc; ++c) {
        const uint4* Ag = (const uint4*)(A + (size_t)rowBase * K + (size_t)c * 64);
        const uint4* Bg = (const uint4*)(Bt + (size_t)colBase * K + (size_t)c * 64);
        #pragma unroll
        for (int it = 0; it < 4; ++it) {
            int i = tid + it * 256;
            int row = i >> 3, q = i & 7;
            *(uint4*)&sA[row * SAS + q * 8] = Ag[(size_t)row * kq + q];
            *(uint4*)&sB[row * SAS + q * 8] = Bg[(size_t)row * kq + q];
        }
        __syncthreads();

        #pragma unroll
        for (int kk = 0; kk < 4; ++kk) {
            const int k0 = kk * 16;
            uint32_t a[2][4];
            #pragma unroll
            for (int mf = 0; mf < 2; ++mf) {
                uint32_t addr = uA + ((mBase + mf * 16 + aRowOff) * SAS + k0 + aKOff) * 2;
                LDSM_X4(a[mf][0], a[mf][1], a[mf][2], a[mf][3], addr);
            }
            #pragma unroll
            for (int nn = 0; nn < 4; ++nn) {
                uint32_t b0, b1, b2, b3;
                uint32_t addr = uB + ((nBase + nn * 16 + bRowOff) * SAS + k0 + bKOff) * 2;
                LDSM_X4(b0, b1, b2, b3, addr);
                #pragma unroll
                for (int mf = 0; mf < 2; ++mf) {
                    MMA_BF16(acc[mf][nn * 2 + 0], a[mf], b0, b1);
                    MMA_BF16(acc[mf][nn * 2 + 1], a[mf], b2, b3);
                }
            }
        }
        __syncthreads();
    }

    const int g4 = lane >> 2, t4 = lane & 3;
    float2 bias2[8];
    #pragma unroll
    for (int nf = 0; nf < 8; ++nf) {
        int col = colBase + nBase + nf * 8 + 2 * t4;
        bias2[nf] = *(const float2*)&bias[col];
    }

    #pragma unroll
    for (int mf = 0; mf < 2; ++mf) {
        #pragma unroll
        for (int rr = 0; rr < 2; ++rr) {
            const int m = rowBase + mBase + mf * 16 + g4 + rr * 8;
            int prow = m;
            if (EPI == 1) {
                int win = m / NTOK, tt = m - win * NTOK;
                int bimg = win >> 6, wloc = win & 63;
                int wh = wloc >> 3, wwi = wloc & 7;
                int ih = tt / WS, iw = tt - ih * WS;
                int h = wh * WS + ih + SHIFT; if (h >= HH) h -= HH;
                int w = wwi * WS + iw + SHIFT; if (w >= WW_) w -= WW_;
                prow = bimg * L_TOK + h * WW_ + w;
            }
            #pragma unroll
            for (int nf = 0; nf < 8; ++nf) {
                const int col = colBase + nBase + nf * 8 + 2 * t4;
                float v0 = acc[mf][nf][rr * 2 + 0] + bias2[nf].x;
                float v1 = acc[mf][nf][rr * 2 + 1] + bias2[nf].y;
                if (EPI == 2) {
                    v0 = 0.5f * v0 * (1.0f + erff(v0 * 0.70710678118654752f));
                    v1 = 0.5f * v1 * (1.0f + erff(v1 * 0.70710678118654752f));
                }
                if (EPI == 0 || EPI == 2) {
                    __nv_bfloat16* C = (__nv_bfloat16*)Cout;
                    uint32_t u = pack_bf2(v0, v1);
                    *(uint32_t*)&C[(size_t)m * N + col] = u;
                } else {
                    float* C = (float*)Cout;
                    const size_t o = (EPI == 1) ? ((size_t)prow * CDIM + col)
                                                : ((size_t)m * N + col);
                    float2 rv = *(const float2*)&res[o];
                    float2 ov; ov.x = v0 + rv.x; ov.y = v1 + rv.y;
                    *(float2*)&C[o] = ov;
                }
            }
        }
    }
}

// ---------------- MMA windowed attention: one block per window ----------
#define SQK 136   // Q/K smem row stride (elements)
#define SVT 72    // Vt smem row stride
#define SPP 72    // P  smem row stride
#define ATTN_SMEM (2 * 64 * SQK * 2 + 128 * SVT * 2 + 8 * 32 * SPP * 2 + 256)

__global__ void __launch_bounds__(256) attn_mma_kernel(
    const __nv_bfloat16* __restrict__ qkv, const float* __restrict__ bias_table,
    __nv_bfloat16* __restrict__ out)
{
    extern __shared__ __align__(16) char dsm[];
    __nv_bfloat16* sQ  = (__nv_bfloat16*)dsm;          // [64][SQK]
    __nv_bfloat16* sK  = sQ + 64 * SQK;                // [64][SQK]
    __nv_bfloat16* sVt = sK + 64 * SQK;                // [128][SVT]  (d, j)
    __nv_bfloat16* sP  = sVt + 128 * SVT;              // 8 warps x [32][SPP]
    unsigned char* sGrp = (unsigned char*)(sP + 8 * 32 * SPP);   // 64
    signed char*   sDiv = (signed char*)(sGrp + 64);             // 64
    signed char*   sMod = (signed char*)(sDiv + 64);             // 64

    const int tid = threadIdx.x, wid = tid >> 5, lane = tid & 31;
    const int win = blockIdx.x;
    const int wloc = win & 63, wh = wloc >> 3, wwi = wloc & 7;
    const __nv_bfloat16* src = qkv + (size_t)win * NTOK * 384;

    // zero Vt (padding columns j>=49 must be 0 for the PV MMA)
    uint32_t* vz = (uint32_t*)sVt;
    for (int i = tid; i < 128 * SVT / 2; i += 256) vz[i] = 0;

    // Q, K rows (49 rows x 128 bf16 = 16 uint4 per row)
    for (int i = tid; i < NTOK * 16; i += 256) {
        int row = i >> 4, q = i & 15;
        uint4 qa = *(const uint4*)(src + (size_t)row * 384 + q * 8);
        uint4 ka = *(const uint4*)(src + (size_t)row * 384 + 128 + q * 8);
        *(uint4*)&sQ[row * SQK + q * 8] = qa;
        *(uint4*)&sK[row * SQK + q * 8] = ka;
    }
    if (tid < 64) {
        int ih = tid / 7, iw = tid % 7;
        sDiv[tid] = (signed char)ih;
        sMod[tid] = (signed char)iw;
        int hs = wh * WS + ih, ws = wwi * WS + iw;
        int gh = hs < (HH - WS) ? 0 : (hs < (HH - SHIFT) ? 1 : 2);
        int gw = ws < (WW_ - WS) ? 0 : (ws < (WW_ - SHIFT) ? 1 : 2);
        sGrp[tid] = (unsigned char)(gh * 3 + gw);
    }
    __syncthreads();

    // V transpose scatter: sVt[d][j] = V[j][d]
    for (int i = tid; i < NTOK * 128; i += 256) {
        int row = i >> 7, d = i & 127;
        sVt[d * SVT + row] = src[(size_t)row * 384 + 256 + d];
    }
    __syncthreads();

    // warp role: head h, row half
    const int h = wid >> 1;
    const int mBase = (wid & 1) * 32;
    const int colQ = h * 32;

    const int mat = lane >> 3;
    const int aRowOff = (lane & 7) + (mat & 1) * 8;
    const int aKOff = (mat >> 1) * 8;
    const int bRowOff = (lane & 7) + ((mat >> 1) & 1) * 8;
    const int bKOff = (mat & 1) * 8;
    const int g4 = lane >> 2, t4 = lane & 3;

    const uint32_t uQ = smem_u32(sQ), uK = smem_u32(sK), uVt = smem_u32(sVt);
    __nv_bfloat16* sPw = sP + wid * 32 * SPP;
    const uint32_t uP = smem_u32(sPw);

    // ---- phase 1: S = Q K^T ----
    float acc[2][8][4];
    #pragma unroll
    for (int i = 0; i < 2; ++i)
        #pragma unroll
        for (int j = 0; j < 8; ++j)
            #pragma unroll
            for (int t = 0; t < 4; ++t) acc[i][j][t] = 0.0f;

    uint32_t a[2][2][4];
    #pragma unroll
    for (int mf = 0; mf < 2; ++mf)
        #pragma unroll
        for (int ks = 0; ks < 2; ++ks) {
            uint32_t addr = uQ + ((mBase + mf * 16 + aRowOff) * SQK + colQ + ks * 16 + aKOff) * 2;
            LDSM_X4(a[mf][ks][0], a[mf][ks][1], a[mf][ks][2], a[mf][ks][3], addr);
        }
    #pragma unroll
    for (int nb = 0; nb < 4; ++nb) {
        uint32_t b[2][4];
        #pragma unroll
        for (int ks = 0; ks < 2; ++ks) {
            uint32_t addr = uK + ((nb * 16 + bRowOff) * SQK + colQ + ks * 16 + bKOff) * 2;
            LDSM_X4(b[ks][0], b[ks][1], b[ks][2], b[ks][3], addr);
        }
        #pragma unroll
        for (int ks = 0; ks < 2; ++ks)
            #pragma unroll
            for (int mf = 0; mf < 2; ++mf) {
                MMA_BF16(acc[mf][nb * 2 + 0], a[mf][ks], b[ks][0], b[ks][1]);
                MMA_BF16(acc[mf][nb * 2 + 1], a[mf][ks], b[ks][2], b[ks][3]);
            }
    }

    // ---- bias + mask + softmax (rows local to lane quad) ----
    const float scale = 0.17677669529663689f;
    int ii[2][2];
    #pragma unroll
    for (int mf = 0; mf < 2; ++mf)
        #pragma unroll
        for (int rr = 0; rr < 2; ++rr) ii[mf][rr] = mBase + mf * 16 + g4 + rr * 8;

    float mx[2][2] = {{-1e30f, -1e30f}, {-1e30f, -1e30f}};
    #pragma unroll
    for (int mf = 0; mf < 2; ++mf)
        #pragma unroll
        for (int nf = 0; nf < 8; ++nf)
            #pragma unroll
            for (int e = 0; e < 4; ++e) {
                int rr = e >> 1;
                int jj = nf * 8 + 2 * t4 + (e & 1);
                float s;
                if (jj < NTOK) {
                    int i0 = ii[mf][rr];
                    int dh = sDiv[i0] - sDiv[jj] + 6;
                    int dw = sMod[i0] - sMod[jj] + 6;
                    float bv = __ldg(&bias_table[(dh * 13 + dw) * NHEAD + h]);
                    float mk = (sGrp[i0] != sGrp[jj]) ? -100.0f : 0.0f;
                    s = acc[mf][nf][e] * scale + bv + mk;
                } else {
                    s = -1e30f;
                }
                acc[mf][nf][e] = s;
                mx[mf][rr] = fmaxf(mx[mf][rr], s);
            }
    #pragma unroll
    for (int mf = 0; mf < 2; ++mf)
        #pragma unroll
        for (int rr = 0; rr < 2; ++rr) {
            float m = mx[mf][rr];
            m = fmaxf(m, __shfl_xor_sync(0xffffffffu, m, 1));
            m = fmaxf(m, __shfl_xor_sync(0xffffffffu, m, 2));
            mx[mf][rr] = m;
        }

    float sm[2][2] = {{0.f, 0.f}, {0.f, 0.f}};
    #pragma unroll
    for (int mf = 0; mf < 2; ++mf)
        #pragma unroll
        for (int nf = 0; nf < 8; ++nf)
            #pragma unroll
            for (int e = 0; e < 4; ++e) {
                int rr = e >> 1;
                float ev = __expf(acc[mf][nf][e] - mx[mf][rr]);
                acc[mf][nf][e] = ev;
                sm[mf][rr] += ev;
            }
    #pragma unroll
    for (int mf = 0; mf < 2; ++mf)
        #pragma unroll
        for (int rr = 0; rr < 2; ++rr) {
            float s = sm[mf][rr];
            s += __shfl_xor_sync(0xffffffffu, s, 1);
            s += __shfl_xor_sync(0xffffffffu, s, 2);
            sm[mf][rr] = s;
        }

    // write unnormalized P (bf16) into this warp's tile
    #pragma unroll
    for (int mf = 0; mf < 2; ++mf)
        #pragma unroll
        for (int rr = 0; rr < 2; ++rr) {
            int prow = mf * 16 + g4 + rr * 8;
            #pragma unroll
            for (int nf = 0; nf < 8; ++nf) {
                uint32_t u = pack_bf2(acc[mf][nf][rr * 2], acc[mf][nf][rr * 2 + 1]);
                *(uint32_t*)&sPw[prow * SPP + nf * 8 + 2 * t4] = u;
            }
        }
    __syncwarp();

    // ---- phase 2: O = P V ----
    float acc2[2][4][4];
    #pragma unroll
    for (int i = 0; i < 2; ++i)
        #pragma unroll
        for (int j = 0; j < 4; ++j)
            #pragma unroll
            for (int t = 0; t < 4; ++t) acc2[i][j][t] = 0.0f;

    #pragma unroll
    for (int kc = 0; kc < 4; ++kc) {
        uint32_t a2[2][4], b2[2][4];
        #pragma unroll
        for (int mf = 0; mf < 2; ++mf) {
            uint32_t addr = uP + ((mf * 16 + aRowOff) * SPP + kc * 16 + aKOff) * 2;
            LDSM_X4(a2[mf][0], a2[mf][1], a2[mf][2], a2[mf][3], addr);
        }
        #pragma unroll
        for (int nb = 0; nb < 2; ++nb) {
            uint32_t addr = uVt + ((colQ + nb * 16 + bRowOff) * SVT + kc * 16 + bKOff) * 2;
            LDSM_X4(b2[nb][0], b2[nb][1], b2[nb][2], b2[nb][3], addr);
        }
        #pragma unroll
        for (int mf = 0; mf < 2; ++mf)
            #pragma unroll
            for (int nb = 0; nb < 2; ++nb) {
                MMA_BF16(acc2[mf][nb * 2 + 0], a2[mf], b2[nb][0], b2[nb][1]);
                MMA_BF16(acc2[mf][nb * 2 + 1], a2[mf], b2[nb][2], b2[nb][3]);
            }
    }

    // ---- epilogue: normalize, store bf16 ----
    #pragma unroll
    for (int mf = 0; mf < 2; ++mf)
        #pragma unroll
        for (int rr = 0; rr < 2; ++rr) {
            int i0 = ii[mf][rr];
            if (i0 < NTOK) {
                float inv = 1.0f / sm[mf][rr];
                __nv_bfloat16* orow = out + ((size_t)win * NTOK + i0) * CDIM + colQ;
                #pragma unroll
                for (int nf = 0; nf < 4; ++nf) {
                    float v0 = acc2[mf][nf][rr * 2 + 0] * inv;
                    float v1 = acc2[mf][nf][rr * 2 + 1] * inv;
                    *(uint32_t*)&orow[nf * 8 + 2 * t4] = pack_bf2(v0, v1);
                }
            }
        }
}

// ---------------- host launcher ----------------
extern "C" void kernel_launch(void* const* d_in, const int* in_sizes, int n_in,
                              void* d_out, int out_size)
{
    const float* x        = (const float*)d_in[0];
    const float* norm1_g  = (const float*)d_in[1];
    const float* norm1_b  = (const float*)d_in[2];
    const float* qkv_w    = (const float*)d_in[3];
    const float* qkv_b    = (const float*)d_in[4];
    const float* rel_tab  = (const float*)d_in[5];
    const float* proj_w   = (const float*)d_in[6];
    const float* proj_b   = (const float*)d_in[7];
    const float* norm2_g  = (const float*)d_in[8];
    const float* norm2_b  = (const float*)d_in[9];
    const float* fc1_w    = (const float*)d_in[10];
    const float* fc1_b    = (const float*)d_in[11];
    const float* fc2_w    = (const float*)d_in[12];
    const float* fc2_b    = (const float*)d_in[13];
    float* out = (float*)d_out;

    __nv_bfloat16 *xwb, *qkvb, *attnb, *hb, *wT;
    float* x1;
    cudaGetSymbolAddress((void**)&xwb,   g_xwb);
    cudaGetSymbolAddress((void**)&qkvb,  g_qkvb);
    cudaGetSymbolAddress((void**)&attnb, g_attnb);
    cudaGetSymbolAddress((void**)&hb,    g_hb);
    cudaGetSymbolAddress((void**)&wT,    g_wT);
    cudaGetSymbolAddress((void**)&x1,    g_x1);

    const int M = M_TOK;

    cudaFuncSetAttribute(attn_mma_kernel, cudaFuncAttributeMaxDynamicSharedMemorySize, ATTN_SMEM);

    // 0) weights -> bf16 [N,K]
    convert_w_kernel<<<WT_TOTAL / 256, 256>>>(qkv_w, proj_w, fc1_w, fc2_w, wT);

    // 1) LN1 + shift + window partition -> bf16
    ln_kernel<<<M / 8, 256>>>(x, norm1_g, norm1_b, xwb, 1);

    // 2) QKV GEMM (HMMA)
    gemm_mma<0><<<dim3(3, M / 128), 256>>>(xwb, wT + WQ_OFF, qkv_b, nullptr, qkvb, M, 384, 128);

    // 3) windowed attention (MMA, one block per window)
    attn_mma_kernel<<<M / NTOK, 256, ATTN_SMEM>>>(qkvb, rel_tab, attnb);

    // 4) proj GEMM + reverse/unshift + residual -> fp32 x1
    gemm_mma<1><<<dim3(1, M / 128), 256>>>(attnb, wT + WP_OFF, proj_b, x, x1, M, 128, 128);

    // 5) LN2 -> bf16
    ln_kernel<<<M / 8, 256>>>(x1, norm2_g, norm2_b, xwb, 0);

    // 6) FC1 GEMM + GELU -> bf16 h
    gemm_mma<2><<<dim3(4, M / 128), 256>>>(xwb, wT + W1_OFF, fc1_b, nullptr, hb, M, 512, 128);

    // 7) FC2 GEMM + residual -> fp32 out
    gemm_mma<3><<<dim3(1, M / 128), 256>>>(hb, wT + W2_OFF, fc2_b, x1, out, M, 128, 512);
}